// round 1
// baseline (speedup 1.0000x reference)
#include <cuda_runtime.h>
#include <cstdint>

// Problem dims (fixed by the dataset)
#define M_DIM 32768   // B*S = 32*1024
#define K_DIM 1152    // IN
#define N_DIM 1152    // OUT
#define R_DIM 64      // LoRA rank
#define QMAXV 255.0f

// ---------------- device scratch (no cudaMalloc allowed) ----------------
__device__ unsigned g_max_enc;
__device__ unsigned g_min_enc;
__device__ float    g_scale;
__device__ float    g_zp;
__device__ float    g_A[(size_t)M_DIM * K_DIM];   // quantized (q - zp) as exact-integer fp32
__device__ float    g_W[(size_t)N_DIM * K_DIM];   // merged weight, pre-rounded to tf32

// Order-preserving float<->uint encoding for atomic min/max
__device__ __forceinline__ unsigned fenc(float f) {
    unsigned u = __float_as_uint(f);
    return (u & 0x80000000u) ? ~u : (u | 0x80000000u);
}
__device__ __forceinline__ float fdec(unsigned u) {
    return (u & 0x80000000u) ? __uint_as_float(u ^ 0x80000000u) : __uint_as_float(~u);
}

// ---------------- kernel 1: reset reduction state ----------------
__global__ void init_kernel() {
    g_max_enc = 0u;            // enc(-inf)
    g_min_enc = 0xFFFFFFFFu;   // enc(+inf)
}

// ---------------- kernel 2: global min/max of x/scales ----------------
__global__ void reduce_kernel(const float* __restrict__ x,
                              const float* __restrict__ scales) {
    const int total4 = (M_DIM * K_DIM) / 4;
    const float INF = __int_as_float(0x7f800000);
    float vmax = -INF, vmin = INF;
    for (int v = blockIdx.x * blockDim.x + threadIdx.x; v < total4;
         v += gridDim.x * blockDim.x) {
        float4 xv = reinterpret_cast<const float4*>(x)[v];
        int k = (v * 4) % K_DIM;                 // K_DIM % 4 == 0
        float a = xv.x / scales[k];
        float b = xv.y / scales[k + 1];
        float c = xv.z / scales[k + 2];
        float d = xv.w / scales[k + 3];
        vmax = fmaxf(vmax, fmaxf(fmaxf(a, b), fmaxf(c, d)));
        vmin = fminf(vmin, fminf(fminf(a, b), fminf(c, d)));
    }
    #pragma unroll
    for (int off = 16; off > 0; off >>= 1) {
        vmax = fmaxf(vmax, __shfl_xor_sync(0xffffffffu, vmax, off));
        vmin = fminf(vmin, __shfl_xor_sync(0xffffffffu, vmin, off));
    }
    __shared__ float smax[8], smin[8];
    int wid = threadIdx.x >> 5, lane = threadIdx.x & 31;
    if (lane == 0) { smax[wid] = vmax; smin[wid] = vmin; }
    __syncthreads();
    if (threadIdx.x == 0) {
        float bm = smax[0], bn = smin[0];
        for (int i = 1; i < (int)(blockDim.x >> 5); i++) {
            bm = fmaxf(bm, smax[i]);
            bn = fminf(bn, smin[i]);
        }
        atomicMax(&g_max_enc, fenc(bm));
        atomicMin(&g_min_enc, fenc(bn));
    }
}

// ---------------- kernel 3: quant params ----------------
__global__ void params_kernel() {
    float mx = fdec(g_max_enc);
    float mn = fdec(g_min_enc);
    float s = (mx - mn) / QMAXV;
    g_scale = s;
    g_zp = rintf(-mn / s);   // round-half-even, matches jnp.round
}

// ---------------- kernel 4: merge W = quant_w + left @ right, round to tf32 ----------------
__global__ void merge_kernel(const float* __restrict__ qw,
                             const float* __restrict__ rw,
                             const float* __restrict__ lw) {
    int idx = blockIdx.x * blockDim.x + threadIdx.x;
    if (idx >= N_DIM * K_DIM) return;
    int n = idx / K_DIM;
    int k = idx - n * K_DIM;
    float acc = qw[idx];
    #pragma unroll 8
    for (int r = 0; r < R_DIM; r++)
        acc = fmaf(lw[n * R_DIM + r], rw[r * K_DIM + k], acc);
    unsigned t;
    asm("cvt.rna.tf32.f32 %0, %1;" : "=r"(t) : "f"(acc));
    g_W[idx] = __uint_as_float(t);
}

// ---------------- kernel 5: quantize A = clip(round(xs/s)+zp,0,255) - zp ----------------
__global__ void quant_kernel(const float* __restrict__ x,
                             const float* __restrict__ scales) {
    const int total4 = (M_DIM * K_DIM) / 4;
    float qs = g_scale;
    float zp = g_zp;
    for (int v = blockIdx.x * blockDim.x + threadIdx.x; v < total4;
         v += gridDim.x * blockDim.x) {
        float4 xv = reinterpret_cast<const float4*>(x)[v];
        int k = (v * 4) % K_DIM;
        float4 o;
        float xs;
        xs = xv.x / scales[k];     o.x = fminf(fmaxf(rintf(xs / qs) + zp, 0.0f), QMAXV) - zp;
        xs = xv.y / scales[k + 1]; o.y = fminf(fmaxf(rintf(xs / qs) + zp, 0.0f), QMAXV) - zp;
        xs = xv.z / scales[k + 2]; o.z = fminf(fmaxf(rintf(xs / qs) + zp, 0.0f), QMAXV) - zp;
        xs = xv.w / scales[k + 3]; o.w = fminf(fmaxf(rintf(xs / qs) + zp, 0.0f), QMAXV) - zp;
        reinterpret_cast<float4*>(g_A)[v] = o;
    }
}

// ---------------- kernel 6: tf32 mma.sync GEMM, out = scale*(A @ W^T) + bias ----------------
#define BM 128
#define BN 128
#define BK 32
#define PAD 4

__global__ __launch_bounds__(256, 2)
void gemm_kernel(const float* __restrict__ bias, float* __restrict__ out) {
    __shared__ float sA[BM][BK + PAD];
    __shared__ float sB[BN][BK + PAD];

    const int tid = threadIdx.x;
    const int lane = tid & 31;
    const int warp = tid >> 5;
    const int warp_m = warp & 1;    // 2 warp rows (64 each)
    const int warp_n = warp >> 1;   // 4 warp cols (32 each)
    const int gid = lane >> 2;      // group id 0..7
    const int tig = lane & 3;       // thread-in-group 0..3

    const int m0 = blockIdx.y * BM;
    const int n0 = blockIdx.x * BN;

    float acc[4][4][4];
    #pragma unroll
    for (int i = 0; i < 4; i++)
        #pragma unroll
        for (int j = 0; j < 4; j++)
            #pragma unroll
            for (int r = 0; r < 4; r++) acc[i][j][r] = 0.0f;

    const int ldrow = tid >> 3;        // 0..31
    const int ldcol = (tid & 7) * 4;   // 0,4,...,28

    const float* Ag = g_A + (size_t)m0 * K_DIM;
    const float* Bg = g_W + (size_t)n0 * K_DIM;

    for (int k0 = 0; k0 < K_DIM; k0 += BK) {
        #pragma unroll
        for (int i = 0; i < 4; i++) {
            int r = ldrow + i * 32;
            float4 av = *reinterpret_cast<const float4*>(Ag + (size_t)r * K_DIM + k0 + ldcol);
            *reinterpret_cast<float4*>(&sA[r][ldcol]) = av;
            float4 bv = *reinterpret_cast<const float4*>(Bg + (size_t)r * K_DIM + k0 + ldcol);
            *reinterpret_cast<float4*>(&sB[r][ldcol]) = bv;
        }
        __syncthreads();

        #pragma unroll
        for (int kk = 0; kk < BK; kk += 8) {
            uint32_t a[4][4], b[4][2];
            #pragma unroll
            for (int im = 0; im < 4; im++) {
                int r = warp_m * 64 + im * 16 + gid;
                a[im][0] = __float_as_uint(sA[r][kk + tig]);
                a[im][1] = __float_as_uint(sA[r + 8][kk + tig]);
                a[im][2] = __float_as_uint(sA[r][kk + 4 + tig]);
                a[im][3] = __float_as_uint(sA[r + 8][kk + 4 + tig]);
            }
            #pragma unroll
            for (int jn = 0; jn < 4; jn++) {
                int c = warp_n * 32 + jn * 8 + gid;
                b[jn][0] = __float_as_uint(sB[c][kk + tig]);
                b[jn][1] = __float_as_uint(sB[c][kk + 4 + tig]);
            }
            #pragma unroll
            for (int im = 0; im < 4; im++)
                #pragma unroll
                for (int jn = 0; jn < 4; jn++) {
                    asm volatile(
                        "mma.sync.aligned.m16n8k8.row.col.f32.tf32.tf32.f32 "
                        "{%0,%1,%2,%3}, {%4,%5,%6,%7}, {%8,%9}, {%0,%1,%2,%3};\n"
                        : "+f"(acc[im][jn][0]), "+f"(acc[im][jn][1]),
                          "+f"(acc[im][jn][2]), "+f"(acc[im][jn][3])
                        : "r"(a[im][0]), "r"(a[im][1]), "r"(a[im][2]), "r"(a[im][3]),
                          "r"(b[jn][0]), "r"(b[jn][1]));
                }
        }
        __syncthreads();
    }

    const float s = g_scale;
    #pragma unroll
    for (int im = 0; im < 4; im++) {
        int m = m0 + warp_m * 64 + im * 16 + gid;
        #pragma unroll
        for (int jn = 0; jn < 4; jn++) {
            int n = n0 + warp_n * 32 + jn * 8 + tig * 2;
            float b0 = bias[n], b1 = bias[n + 1];
            float2 v0, v1;
            v0.x = acc[im][jn][0] * s + b0;
            v0.y = acc[im][jn][1] * s + b1;
            v1.x = acc[im][jn][2] * s + b0;
            v1.y = acc[im][jn][3] * s + b1;
            *reinterpret_cast<float2*>(out + (size_t)m * N_DIM + n) = v0;
            *reinterpret_cast<float2*>(out + (size_t)(m + 8) * N_DIM + n) = v1;
        }
    }
}

// ---------------- launch ----------------
extern "C" void kernel_launch(void* const* d_in, const int* in_sizes, int n_in,
                              void* d_out, int out_size) {
    const float* x      = (const float*)d_in[0];
    const float* qw     = (const float*)d_in[1];
    const float* rw     = (const float*)d_in[2];
    const float* lw     = (const float*)d_in[3];
    const float* bias   = (const float*)d_in[4];
    const float* scales = (const float*)d_in[5];
    float* out = (float*)d_out;

    init_kernel<<<1, 1>>>();
    reduce_kernel<<<2304, 256>>>(x, scales);
    params_kernel<<<1, 1>>>();
    merge_kernel<<<(N_DIM * K_DIM + 255) / 256, 256>>>(qw, rw, lw);
    quant_kernel<<<2304, 256>>>(x, scales);
    gemm_kernel<<<dim3(N_DIM / BN, M_DIM / BM), 256>>>(bias, out);
}

// round 4
// speedup vs baseline: 1.5696x; 1.5696x over previous
#include <cuda_runtime.h>
#include <cuda_fp16.h>
#include <cstdint>

// Problem dims (fixed by the dataset)
#define M_DIM 32768   // B*S
#define K_DIM 1152
#define N_DIM 1152
#define R_DIM 64
#define QMAXV 255.0f

// ---------------- device scratch ----------------
__device__ unsigned g_max_enc;
__device__ unsigned g_min_enc;
__device__ float    g_scale;
__device__ float    g_zp;
__device__ __align__(16) __half g_A[(size_t)M_DIM * K_DIM];  // (q-zp): exact int, exact in fp16
__device__ __align__(16) __half g_W[(size_t)N_DIM * K_DIM];  // merged weight in fp16

// Order-preserving float<->uint encoding for atomic min/max
__device__ __forceinline__ unsigned fenc(float f) {
    unsigned u = __float_as_uint(f);
    return (u & 0x80000000u) ? ~u : (u | 0x80000000u);
}
__device__ __forceinline__ float fdec(unsigned u) {
    return (u & 0x80000000u) ? __uint_as_float(u ^ 0x80000000u) : __uint_as_float(~u);
}

__device__ __forceinline__ uint32_t smem_u32(const void* p) {
    uint32_t a;
    asm("{ .reg .u64 t; cvta.to.shared.u64 t, %1; cvt.u32.u64 %0, t; }" : "=r"(a) : "l"(p));
    return a;
}

#define CP_ASYNC16(saddr, gptr) \
    asm volatile("cp.async.cg.shared.global [%0], [%1], 16;" :: "r"(saddr), "l"(gptr) : "memory")
#define CP_COMMIT() asm volatile("cp.async.commit_group;" ::: "memory")
#define CP_WAIT3()  asm volatile("cp.async.wait_group 3;" ::: "memory")

// ---------------- kernel 1: reset reduction state ----------------
__global__ void init_kernel() {
    g_max_enc = 0u;
    g_min_enc = 0xFFFFFFFFu;
}

// ---------------- kernel 2: global min/max of x/scales ----------------
__global__ void reduce_kernel(const float* __restrict__ x,
                              const float* __restrict__ scales) {
    const int total4 = (M_DIM * K_DIM) / 4;
    const float INF = __int_as_float(0x7f800000);
    float vmax = -INF, vmin = INF;
    for (int v = blockIdx.x * blockDim.x + threadIdx.x; v < total4;
         v += gridDim.x * blockDim.x) {
        float4 xv = reinterpret_cast<const float4*>(x)[v];
        int k = (v * 4) % K_DIM;
        float a = xv.x / scales[k];
        float b = xv.y / scales[k + 1];
        float c = xv.z / scales[k + 2];
        float d = xv.w / scales[k + 3];
        vmax = fmaxf(vmax, fmaxf(fmaxf(a, b), fmaxf(c, d)));
        vmin = fminf(vmin, fminf(fminf(a, b), fminf(c, d)));
    }
    #pragma unroll
    for (int off = 16; off > 0; off >>= 1) {
        vmax = fmaxf(vmax, __shfl_xor_sync(0xffffffffu, vmax, off));
        vmin = fminf(vmin, __shfl_xor_sync(0xffffffffu, vmin, off));
    }
    __shared__ float smax[8], smin[8];
    int wid = threadIdx.x >> 5, lane = threadIdx.x & 31;
    if (lane == 0) { smax[wid] = vmax; smin[wid] = vmin; }
    __syncthreads();
    if (threadIdx.x == 0) {
        float bm = smax[0], bn = smin[0];
        for (int i = 1; i < (int)(blockDim.x >> 5); i++) {
            bm = fmaxf(bm, smax[i]);
            bn = fminf(bn, smin[i]);
        }
        atomicMax(&g_max_enc, fenc(bm));
        atomicMin(&g_min_enc, fenc(bn));
    }
}

// ---------------- kernel 3: quant params ----------------
__global__ void params_kernel() {
    float mx = fdec(g_max_enc);
    float mn = fdec(g_min_enc);
    float s = (mx - mn) / QMAXV;
    g_scale = s;
    g_zp = rintf(-mn / s);
}

// ---------------- kernel 4: merge W = quant_w + left @ right -> fp16 ----------------
__global__ void merge_kernel(const float* __restrict__ qw,
                             const float* __restrict__ rw,
                             const float* __restrict__ lw) {
    int idx = blockIdx.x * blockDim.x + threadIdx.x;
    if (idx >= N_DIM * K_DIM) return;
    int n = idx / K_DIM;
    int k = idx - n * K_DIM;
    float acc = qw[idx];
    #pragma unroll 8
    for (int r = 0; r < R_DIM; r++)
        acc = fmaf(lw[n * R_DIM + r], rw[r * K_DIM + k], acc);
    g_W[idx] = __float2half_rn(acc);
}

// ---------------- kernel 5: quantize A (fp16 output) ----------------
__global__ void quant_kernel(const float* __restrict__ x,
                             const float* __restrict__ scales) {
    const int total8 = (M_DIM * K_DIM) / 8;
    float qs = g_scale;
    float zp = g_zp;
    for (int v = blockIdx.x * blockDim.x + threadIdx.x; v < total8;
         v += gridDim.x * blockDim.x) {
        float4 x0 = reinterpret_cast<const float4*>(x)[2 * v];
        float4 x1 = reinterpret_cast<const float4*>(x)[2 * v + 1];
        int k = (v * 8) % K_DIM;
        float f[8];
        f[0] = x0.x / scales[k];     f[1] = x0.y / scales[k + 1];
        f[2] = x0.z / scales[k + 2]; f[3] = x0.w / scales[k + 3];
        f[4] = x1.x / scales[k + 4]; f[5] = x1.y / scales[k + 5];
        f[6] = x1.z / scales[k + 6]; f[7] = x1.w / scales[k + 7];
        #pragma unroll
        for (int j = 0; j < 8; j++)
            f[j] = fminf(fmaxf(rintf(f[j] / qs) + zp, 0.0f), QMAXV) - zp;
        __half2 p0 = __floats2half2_rn(f[0], f[1]);
        __half2 p1 = __floats2half2_rn(f[2], f[3]);
        __half2 p2 = __floats2half2_rn(f[4], f[5]);
        __half2 p3 = __floats2half2_rn(f[6], f[7]);
        uint4 u;
        u.x = *reinterpret_cast<unsigned*>(&p0);
        u.y = *reinterpret_cast<unsigned*>(&p1);
        u.z = *reinterpret_cast<unsigned*>(&p2);
        u.w = *reinterpret_cast<unsigned*>(&p3);
        reinterpret_cast<uint4*>(g_A)[v] = u;
    }
}

// ---------------- kernel 6: fp16 mma.sync GEMM, out = s*(A @ W^T) + bias ----------------
#define BM 128
#define BN 128
#define BK 64                          // 64 halves = 128 bytes payload / row
#define NSTAGES 4
#define KITERS (K_DIM / BK)            // 18
#define PADH 72                        // padded halves per row
#define PADB (PADH * 2)                // 144 bytes (16B aligned, conflict-free)
#define TILE_BYTES (128 * PADB)        // 18432
#define STAGE_BYTES (2 * TILE_BYTES)   // A + B = 36864
#define SMEM_DYN (NSTAGES * STAGE_BYTES)   // 147456

__device__ __forceinline__ void ldm_x4(uint32_t* d, uint32_t addr) {
    asm volatile("ldmatrix.sync.aligned.m8n8.x4.shared.b16 {%0,%1,%2,%3}, [%4];"
                 : "=r"(d[0]), "=r"(d[1]), "=r"(d[2]), "=r"(d[3]) : "r"(addr));
}
__device__ __forceinline__ void hmma16816(float* c, const uint32_t* a, const uint32_t* b) {
    asm volatile(
        "mma.sync.aligned.m16n8k16.row.col.f32.f16.f16.f32 "
        "{%0,%1,%2,%3}, {%4,%5,%6,%7}, {%8,%9}, {%0,%1,%2,%3};\n"
        : "+f"(c[0]), "+f"(c[1]), "+f"(c[2]), "+f"(c[3])
        : "r"(a[0]), "r"(a[1]), "r"(a[2]), "r"(a[3]), "r"(b[0]), "r"(b[1]));
}

// Load one stage (128 rows x 8 16B-chunks per tile, 256 threads -> 4 chunks each)
__device__ __forceinline__ void load_stage(uint32_t sA, uint32_t sB,
                                           const __half* Ag, const __half* Bg,
                                           int k0, int tid) {
    #pragma unroll
    for (int q = 0; q < 4; q++) {
        int c = q * 256 + tid;            // 0..1023
        int row = c >> 3;                 // 0..127
        int col16 = c & 7;                // 0..7
        uint32_t soff = (uint32_t)row * PADB + col16 * 16;
        CP_ASYNC16(sA + soff, Ag + (size_t)row * K_DIM + k0 + col16 * 8);
        CP_ASYNC16(sB + soff, Bg + (size_t)row * K_DIM + k0 + col16 * 8);
    }
}

__global__ __launch_bounds__(256, 1)
void gemm_kernel(const float* __restrict__ bias, float* __restrict__ out) {
    extern __shared__ char dsmem[];
    const uint32_t sbase = smem_u32(dsmem);

    const int tid = threadIdx.x;
    const int lane = tid & 31;
    const int warp = tid >> 5;
    const int warp_m = warp & 1;    // 2 warp rows (64 rows each)
    const int warp_n = warp >> 1;   // 4 warp cols (32 cols each)
    const int gid = lane >> 2;
    const int tig = lane & 3;

    const int m0 = blockIdx.y * BM;
    const int n0 = blockIdx.x * BN;
    const __half* Ag = g_A + (size_t)m0 * K_DIM;
    const __half* Bg = g_W + (size_t)n0 * K_DIM;

    float acc[4][4][4];
    #pragma unroll
    for (int i = 0; i < 4; i++)
        #pragma unroll
        for (int j = 0; j < 4; j++)
            #pragma unroll
            for (int r = 0; r < 4; r++) acc[i][j][r] = 0.0f;

    // ldmatrix per-lane address components (verified m16n8k16 fragment layouts)
    const int lane15 = lane & 15;
    const int laneHiA = (lane >> 4) * 16;              // +16B => k+8 (A a2/a3)
    const uint32_t aLaneOff = (uint32_t)(warp_m * 64 + lane15) * PADB + laneHiA;
    const int rowB = warp_n * 32 + (lane >> 4) * 8 + (lane & 7);
    const int kaddB = ((lane >> 3) & 1) * 16;          // lanes 8-15 => k+8
    const uint32_t bLaneOff = (uint32_t)rowB * PADB + kaddB;

    // prologue: prefetch NSTAGES stages
    #pragma unroll
    for (int st = 0; st < NSTAGES; st++) {
        const uint32_t sA = sbase + st * STAGE_BYTES;
        load_stage(sA, sA + TILE_BYTES, Ag, Bg, st * BK, tid);
        CP_COMMIT();
    }

    int sidx = 0;
    for (int it = 0; it < KITERS; ++it) {
        CP_WAIT3();
        __syncthreads();

        const uint32_t sA = sbase + sidx * STAGE_BYTES;
        const uint32_t sB = sA + TILE_BYTES;

        #pragma unroll
        for (int ks = 0; ks < 4; ks++) {
            uint32_t a[4][4], b[2][4];
            #pragma unroll
            for (int im = 0; im < 4; im++)
                ldm_x4(a[im], sA + aLaneOff + (uint32_t)im * 16 * PADB + ks * 32);
            #pragma unroll
            for (int j2 = 0; j2 < 2; j2++)
                ldm_x4(b[j2], sB + bLaneOff + (uint32_t)j2 * 16 * PADB + ks * 32);
            #pragma unroll
            for (int im = 0; im < 4; im++) {
                hmma16816(acc[im][0], a[im], &b[0][0]);
                hmma16816(acc[im][1], a[im], &b[0][2]);
                hmma16816(acc[im][2], a[im], &b[1][0]);
                hmma16816(acc[im][3], a[im], &b[1][2]);
            }
        }
        __syncthreads();

        const int itn = it + NSTAGES;
        if (itn < KITERS) {
            load_stage(sA, sB, Ag, Bg, itn * BK, tid);   // reuse current buffer
        }
        CP_COMMIT();

        sidx = (sidx + 1 == NSTAGES) ? 0 : sidx + 1;
    }

    // epilogue: out = acc * scale + bias
    const float s = g_scale;
    #pragma unroll
    for (int im = 0; im < 4; im++) {
        int m = m0 + warp_m * 64 + im * 16 + gid;
        #pragma unroll
        for (int jn = 0; jn < 4; jn++) {
            int n = n0 + warp_n * 32 + jn * 8 + tig * 2;
            float b0 = bias[n], b1 = bias[n + 1];
            float2 v0, v1;
            v0.x = acc[im][jn][0] * s + b0;
            v0.y = acc[im][jn][1] * s + b1;
            v1.x = acc[im][jn][2] * s + b0;
            v1.y = acc[im][jn][3] * s + b1;
            *reinterpret_cast<float2*>(out + (size_t)m * N_DIM + n) = v0;
            *reinterpret_cast<float2*>(out + (size_t)(m + 8) * N_DIM + n) = v1;
        }
    }
}

// ---------------- launch ----------------
extern "C" void kernel_launch(void* const* d_in, const int* in_sizes, int n_in,
                              void* d_out, int out_size) {
    const float* x      = (const float*)d_in[0];
    const float* qw     = (const float*)d_in[1];
    const float* rw     = (const float*)d_in[2];
    const float* lw     = (const float*)d_in[3];
    const float* bias   = (const float*)d_in[4];
    const float* scales = (const float*)d_in[5];
    float* out = (float*)d_out;

    static bool attr_done = false;
    if (!attr_done) {
        cudaFuncSetAttribute(gemm_kernel, cudaFuncAttributeMaxDynamicSharedMemorySize, SMEM_DYN);
        attr_done = true;
    }

    init_kernel<<<1, 1>>>();
    reduce_kernel<<<2304, 256>>>(x, scales);
    params_kernel<<<1, 1>>>();
    merge_kernel<<<(N_DIM * K_DIM + 255) / 256, 256>>>(qw, rw, lw);
    quant_kernel<<<1152, 256>>>(x, scales);
    gemm_kernel<<<dim3(N_DIM / BN, M_DIM / BM), 256, SMEM_DYN>>>(bias, out);
}

// round 5
// speedup vs baseline: 1.6009x; 1.0200x over previous
#include <cuda_runtime.h>
#include <cuda_fp16.h>
#include <cstdint>

// Problem dims (fixed by the dataset)
#define M_DIM 32768   // B*S
#define K_DIM 1152
#define N_DIM 1152
#define R_DIM 64
#define QMAXV 255.0f

// ---------------- device scratch ----------------
__device__ unsigned g_max_enc;
__device__ unsigned g_min_enc;
__device__ float    g_scale;
__device__ float    g_zp;
__device__ __align__(16) __half g_A[(size_t)M_DIM * K_DIM];  // (q-zp): exact int, exact in fp16
__device__ __align__(16) __half g_W[(size_t)N_DIM * K_DIM];  // merged weight in fp16

// Order-preserving float<->uint encoding for atomic min/max
__device__ __forceinline__ unsigned fenc(float f) {
    unsigned u = __float_as_uint(f);
    return (u & 0x80000000u) ? ~u : (u | 0x80000000u);
}
__device__ __forceinline__ float fdec(unsigned u) {
    return (u & 0x80000000u) ? __uint_as_float(u ^ 0x80000000u) : __uint_as_float(~u);
}

__device__ __forceinline__ uint32_t smem_u32(const void* p) {
    uint32_t a;
    asm("{ .reg .u64 t; cvta.to.shared.u64 t, %1; cvt.u32.u64 %0, t; }" : "=r"(a) : "l"(p));
    return a;
}

#define CP_ASYNC16(saddr, gptr) \
    asm volatile("cp.async.cg.shared.global [%0], [%1], 16;" :: "r"(saddr), "l"(gptr) : "memory")
#define CP_COMMIT() asm volatile("cp.async.commit_group;" ::: "memory")
#define CP_WAIT2()  asm volatile("cp.async.wait_group 2;" ::: "memory")

// ---------------- kernel 1: reset reduction state ----------------
__global__ void init_kernel() {
    g_max_enc = 0u;
    g_min_enc = 0xFFFFFFFFu;
}

// ---------------- kernel 2: global min/max of x/scales ----------------
__global__ void reduce_kernel(const float* __restrict__ x,
                              const float* __restrict__ scales) {
    const int total4 = (M_DIM * K_DIM) / 4;
    const float INF = __int_as_float(0x7f800000);
    float vmax = -INF, vmin = INF;
    for (int v = blockIdx.x * blockDim.x + threadIdx.x; v < total4;
         v += gridDim.x * blockDim.x) {
        float4 xv = reinterpret_cast<const float4*>(x)[v];
        int k = (v * 4) % K_DIM;
        float a = xv.x / scales[k];
        float b = xv.y / scales[k + 1];
        float c = xv.z / scales[k + 2];
        float d = xv.w / scales[k + 3];
        vmax = fmaxf(vmax, fmaxf(fmaxf(a, b), fmaxf(c, d)));
        vmin = fminf(vmin, fminf(fminf(a, b), fminf(c, d)));
    }
    #pragma unroll
    for (int off = 16; off > 0; off >>= 1) {
        vmax = fmaxf(vmax, __shfl_xor_sync(0xffffffffu, vmax, off));
        vmin = fminf(vmin, __shfl_xor_sync(0xffffffffu, vmin, off));
    }
    __shared__ float smax[8], smin[8];
    int wid = threadIdx.x >> 5, lane = threadIdx.x & 31;
    if (lane == 0) { smax[wid] = vmax; smin[wid] = vmin; }
    __syncthreads();
    if (threadIdx.x == 0) {
        float bm = smax[0], bn = smin[0];
        for (int i = 1; i < (int)(blockDim.x >> 5); i++) {
            bm = fmaxf(bm, smax[i]);
            bn = fminf(bn, smin[i]);
        }
        atomicMax(&g_max_enc, fenc(bm));
        atomicMin(&g_min_enc, fenc(bn));
    }
}

// ---------------- kernel 3: quant params ----------------
__global__ void params_kernel() {
    float mx = fdec(g_max_enc);
    float mn = fdec(g_min_enc);
    float s = (mx - mn) / QMAXV;
    g_scale = s;
    g_zp = rintf(-mn / s);
}

// ---------------- kernel 4: merge W = quant_w + left @ right -> fp16 ----------------
__global__ void merge_kernel(const float* __restrict__ qw,
                             const float* __restrict__ rw,
                             const float* __restrict__ lw) {
    int idx = blockIdx.x * blockDim.x + threadIdx.x;
    if (idx >= N_DIM * K_DIM) return;
    int n = idx / K_DIM;
    int k = idx - n * K_DIM;
    float acc = qw[idx];
    #pragma unroll 8
    for (int r = 0; r < R_DIM; r++)
        acc = fmaf(lw[n * R_DIM + r], rw[r * K_DIM + k], acc);
    g_W[idx] = __float2half_rn(acc);
}

// ---------------- kernel 5: quantize A (fp16 output) ----------------
__global__ void quant_kernel(const float* __restrict__ x,
                             const float* __restrict__ scales) {
    const int total8 = (M_DIM * K_DIM) / 8;
    float qs = g_scale;
    float zp = g_zp;
    for (int v = blockIdx.x * blockDim.x + threadIdx.x; v < total8;
         v += gridDim.x * blockDim.x) {
        float4 x0 = reinterpret_cast<const float4*>(x)[2 * v];
        float4 x1 = reinterpret_cast<const float4*>(x)[2 * v + 1];
        int k = (v * 8) % K_DIM;
        float f[8];
        f[0] = x0.x / scales[k];     f[1] = x0.y / scales[k + 1];
        f[2] = x0.z / scales[k + 2]; f[3] = x0.w / scales[k + 3];
        f[4] = x1.x / scales[k + 4]; f[5] = x1.y / scales[k + 5];
        f[6] = x1.z / scales[k + 6]; f[7] = x1.w / scales[k + 7];
        #pragma unroll
        for (int j = 0; j < 8; j++)
            f[j] = fminf(fmaxf(rintf(f[j] / qs) + zp, 0.0f), QMAXV) - zp;
        __half2 p0 = __floats2half2_rn(f[0], f[1]);
        __half2 p1 = __floats2half2_rn(f[2], f[3]);
        __half2 p2 = __floats2half2_rn(f[4], f[5]);
        __half2 p3 = __floats2half2_rn(f[6], f[7]);
        uint4 u;
        u.x = *reinterpret_cast<unsigned*>(&p0);
        u.y = *reinterpret_cast<unsigned*>(&p1);
        u.z = *reinterpret_cast<unsigned*>(&p2);
        u.w = *reinterpret_cast<unsigned*>(&p3);
        reinterpret_cast<uint4*>(g_A)[v] = u;
    }
}

// ---------------- kernel 6: fp16 mma.sync GEMM, out = s*(A @ W^T) + bias ----------------
#define BM 128
#define BN 128
#define BK 64                          // 64 halves = 128 bytes payload / row
#define NSTAGES 4
#define KITERS (K_DIM / BK)            // 18
#define PADH 72                        // padded halves per row
#define PADB (PADH * 2)                // 144 bytes (16B aligned, conflict-free)
#define TILE_BYTES (128 * PADB)        // 18432
#define STAGE_BYTES (2 * TILE_BYTES)   // A + B = 36864
#define SMEM_DYN (NSTAGES * STAGE_BYTES)   // 147456

__device__ __forceinline__ void ldm_x4(uint32_t* d, uint32_t addr) {
    asm volatile("ldmatrix.sync.aligned.m8n8.x4.shared.b16 {%0,%1,%2,%3}, [%4];"
                 : "=r"(d[0]), "=r"(d[1]), "=r"(d[2]), "=r"(d[3]) : "r"(addr));
}
__device__ __forceinline__ void hmma16816(float* c, const uint32_t* a, const uint32_t* b) {
    asm volatile(
        "mma.sync.aligned.m16n8k16.row.col.f32.f16.f16.f32 "
        "{%0,%1,%2,%3}, {%4,%5,%6,%7}, {%8,%9}, {%0,%1,%2,%3};\n"
        : "+f"(c[0]), "+f"(c[1]), "+f"(c[2]), "+f"(c[3])
        : "r"(a[0]), "r"(a[1]), "r"(a[2]), "r"(a[3]), "r"(b[0]), "r"(b[1]));
}

// Load one stage (128 rows x 8 16B-chunks per tile, 256 threads -> 4 chunks each)
__device__ __forceinline__ void load_stage(uint32_t sA, uint32_t sB,
                                           const __half* Ag, const __half* Bg,
                                           int k0, int tid) {
    #pragma unroll
    for (int q = 0; q < 4; q++) {
        int c = q * 256 + tid;            // 0..1023
        int row = c >> 3;                 // 0..127
        int col16 = c & 7;                // 0..7
        uint32_t soff = (uint32_t)row * PADB + col16 * 16;
        CP_ASYNC16(sA + soff, Ag + (size_t)row * K_DIM + k0 + col16 * 8);
        CP_ASYNC16(sB + soff, Bg + (size_t)row * K_DIM + k0 + col16 * 8);
    }
}

__global__ __launch_bounds__(256, 1)
void gemm_kernel(const float* __restrict__ bias, float* __restrict__ out) {
    extern __shared__ char dsmem[];
    const uint32_t sbase = smem_u32(dsmem);

    const int tid = threadIdx.x;
    const int lane = tid & 31;
    const int warp = tid >> 5;
    const int warp_m = warp & 1;    // 2 warp rows (64 rows each)
    const int warp_n = warp >> 1;   // 4 warp cols (32 cols each)
    const int gid = lane >> 2;
    const int tig = lane & 3;

    const int m0 = blockIdx.y * BM;
    const int n0 = blockIdx.x * BN;
    const __half* Ag = g_A + (size_t)m0 * K_DIM;
    const __half* Bg = g_W + (size_t)n0 * K_DIM;

    float acc[4][4][4];
    #pragma unroll
    for (int i = 0; i < 4; i++)
        #pragma unroll
        for (int j = 0; j < 4; j++)
            #pragma unroll
            for (int r = 0; r < 4; r++) acc[i][j][r] = 0.0f;

    // ldmatrix per-lane address components (m16n8k16 fragment layouts)
    const int lane15 = lane & 15;
    const int laneHiA = (lane >> 4) * 16;              // +16B => k+8 (A a2/a3)
    const uint32_t aLaneOff = (uint32_t)(warp_m * 64 + lane15) * PADB + laneHiA;
    const int rowB = warp_n * 32 + (lane >> 4) * 8 + (lane & 7);
    const int kaddB = ((lane >> 3) & 1) * 16;          // lanes 8-15 => k+8
    const uint32_t bLaneOff = (uint32_t)rowB * PADB + kaddB;

    // prologue: prefetch NSTAGES-1 stages (buffers 0..2)
    #pragma unroll
    for (int st = 0; st < NSTAGES - 1; st++) {
        const uint32_t sA = sbase + st * STAGE_BYTES;
        load_stage(sA, sA + TILE_BYTES, Ag, Bg, st * BK, tid);
        CP_COMMIT();
    }

    for (int it = 0; it < KITERS; ++it) {
        CP_WAIT2();                 // stage `it` resident
        __syncthreads();            // all warps done with buffer (it-1)%4, stage it visible

        const int cbuf = it & (NSTAGES - 1);
        const uint32_t sA = sbase + cbuf * STAGE_BYTES;
        const uint32_t sB = sA + TILE_BYTES;

        // prefetch stage it+3 into buffer freed at iteration it-1
        const int itn = it + NSTAGES - 1;
        if (itn < KITERS) {
            const int fbuf = itn & (NSTAGES - 1);
            const uint32_t fA = sbase + fbuf * STAGE_BYTES;
            load_stage(fA, fA + TILE_BYTES, Ag, Bg, itn * BK, tid);
        }
        CP_COMMIT();

        #pragma unroll
        for (int ks = 0; ks < 4; ks++) {
            uint32_t a[4][4], b[2][4];
            #pragma unroll
            for (int im = 0; im < 4; im++)
                ldm_x4(a[im], sA + aLaneOff + (uint32_t)im * 16 * PADB + ks * 32);
            #pragma unroll
            for (int j2 = 0; j2 < 2; j2++)
                ldm_x4(b[j2], sB + bLaneOff + (uint32_t)j2 * 16 * PADB + ks * 32);
            #pragma unroll
            for (int im = 0; im < 4; im++) {
                hmma16816(acc[im][0], a[im], &b[0][0]);
                hmma16816(acc[im][1], a[im], &b[0][2]);
                hmma16816(acc[im][2], a[im], &b[1][0]);
                hmma16816(acc[im][3], a[im], &b[1][2]);
            }
        }
    }

    // epilogue: out = acc * scale + bias
    const float s = g_scale;
    #pragma unroll
    for (int im = 0; im < 4; im++) {
        int m = m0 + warp_m * 64 + im * 16 + gid;
        #pragma unroll
        for (int jn = 0; jn < 4; jn++) {
            int n = n0 + warp_n * 32 + jn * 8 + tig * 2;
            float b0 = bias[n], b1 = bias[n + 1];
            float2 v0, v1;
            v0.x = acc[im][jn][0] * s + b0;
            v0.y = acc[im][jn][1] * s + b1;
            v1.x = acc[im][jn][2] * s + b0;
            v1.y = acc[im][jn][3] * s + b1;
            *reinterpret_cast<float2*>(out + (size_t)m * N_DIM + n) = v0;
            *reinterpret_cast<float2*>(out + (size_t)(m + 8) * N_DIM + n) = v1;
        }
    }
}

// ---------------- launch ----------------
extern "C" void kernel_launch(void* const* d_in, const int* in_sizes, int n_in,
                              void* d_out, int out_size) {
    const float* x      = (const float*)d_in[0];
    const float* qw     = (const float*)d_in[1];
    const float* rw     = (const float*)d_in[2];
    const float* lw     = (const float*)d_in[3];
    const float* bias   = (const float*)d_in[4];
    const float* scales = (const float*)d_in[5];
    float* out = (float*)d_out;

    static cudaStream_t s2 = nullptr;
    static cudaEvent_t ev_fork = nullptr, ev_join = nullptr;
    static bool init_done = false;
    if (!init_done) {
        cudaFuncSetAttribute(gemm_kernel, cudaFuncAttributeMaxDynamicSharedMemorySize, SMEM_DYN);
        cudaStreamCreateWithFlags(&s2, cudaStreamNonBlocking);
        cudaEventCreateWithFlags(&ev_fork, cudaEventDisableTiming);
        cudaEventCreateWithFlags(&ev_join, cudaEventDisableTiming);
        init_done = true;
    }

    // fork: merge (independent) runs on s2, overlapping the reduce->quant chain
    cudaEventRecord(ev_fork, 0);
    cudaStreamWaitEvent(s2, ev_fork, 0);
    merge_kernel<<<(N_DIM * K_DIM + 255) / 256, 256, 0, s2>>>(qw, rw, lw);
    cudaEventRecord(ev_join, s2);

    // main chain (legacy default stream)
    init_kernel<<<1, 1>>>();
    reduce_kernel<<<2304, 256>>>(x, scales);
    params_kernel<<<1, 1>>>();
    quant_kernel<<<1152, 256>>>(x, scales);

    // join, then GEMM
    cudaStreamWaitEvent(0, ev_join, 0);
    gemm_kernel<<<dim3(N_DIM / BN, M_DIM / BM), 256, SMEM_DYN>>>(bias, out);
}